// round 3
// baseline (speedup 1.0000x reference)
#include <cuda_runtime.h>
#include <cuda_bf16.h>

// ---------------- problem constants ----------------
#define B_BATCH 64
#define N_NODES 1024
#define S_LOC   12
#define HID     64
#define PAT     32
#define M_GLB   64
#define S_GLB   6
#define M_LOC   64
#define D_EMB   16
#define KDIM    768           // S_LOC * HID
#define CDIM    128           // M_LOC + M_GLB
#define ROWS    65536         // B_BATCH * N_NODES

// ---------------- static device scratch (no allocations allowed) ----------------
__device__ __align__(16) float g_A[KDIM * CDIM];          // folded weights  [768][128]
__device__ __align__(16) float g_bias[CDIM];              // b_q contribution to logits
__device__ __align__(16) float g_Lm[M_LOC * PAT];         // local bank mean  [64][32]
__device__ __align__(16) float g_Gm[M_GLB * PAT];         // global bank mean [64][32]
__device__ __align__(16) float g_nw[N_NODES * 64 * HID];  // node weights [1024][64][64]
__device__ __align__(16) float g_sim[(size_t)ROWS * CDIM];// logits [65536][128]

// ================= P1: A[k][c] = folded bank weights =================
// k = s*64 + h.  c<64: local  A = sum_p Wq[h][p]*L[c][s][p]
//                c>=64: global A = 0.5 * sum_p Wq[h][p]*G[c-64][s/2][p]
__global__ void pA_kernel(const float* __restrict__ G, const float* __restrict__ L,
                          const float* __restrict__ Wq) {
    int t = blockIdx.x * 256 + threadIdx.x;          // < 98304 = 768*128
    int k = t >> 7, c = t & 127;
    int s = k >> 6, h = k & 63;
    const float* wp = Wq + h * PAT;
    float v = 0.f;
    if (c < 64) {
        const float* lp = L + c * (S_LOC * PAT) + s * PAT;
        #pragma unroll
        for (int p = 0; p < PAT; p++) v += wp[p] * lp[p];
    } else {
        const float* gp = G + (c - 64) * (S_GLB * PAT) + (s >> 1) * PAT;
        #pragma unroll
        for (int p = 0; p < PAT; p++) v += wp[p] * gp[p];
        v *= 0.5f;
    }
    g_A[k * CDIM + c] = v;
}

// ================= P2: bias[c] = b_q contribution =================
__global__ void pBias_kernel(const float* __restrict__ G, const float* __restrict__ L,
                             const float* __restrict__ bq) {
    int c = threadIdx.x;                              // 128 threads
    float v = 0.f;
    if (c < 64) {
        for (int s = 0; s < S_LOC; s++)
            #pragma unroll
            for (int p = 0; p < PAT; p++) v += bq[p] * L[c * (S_LOC * PAT) + s * PAT + p];
    } else {
        // pooled-q dot G: bias of pooled q is just b_q (mean of constant)
        for (int s = 0; s < S_GLB; s++)
            #pragma unroll
            for (int p = 0; p < PAT; p++) v += bq[p] * G[(c - 64) * (S_GLB * PAT) + s * PAT + p];
    }
    g_bias[c] = v;
}

// ================= P3: bank means over s =================
__global__ void pMean_kernel(const float* __restrict__ G, const float* __restrict__ L) {
    int idx = blockIdx.x * 256 + threadIdx.x;         // < 2048
    if (idx >= 2048) return;
    int m = idx >> 5, p = idx & 31;
    float lm = 0.f, gm = 0.f;
    for (int s = 0; s < S_LOC; s++) lm += L[m * (S_LOC * PAT) + s * PAT + p];
    for (int s = 0; s < S_GLB; s++) gm += G[m * (S_GLB * PAT) + s * PAT + p];
    g_Lm[idx] = lm * (1.f / 12.f);
    g_Gm[idx] = gm * (1.f / 6.f);
}

// ================= P4: node_w[n][f][h] = sum_d emb[n][d]*pool[d][f][h] =================
__global__ void pNw_kernel(const float* __restrict__ emb, const float* __restrict__ pool) {
    __shared__ float e[D_EMB];
    int n = blockIdx.x, t = threadIdx.x;
    if (t < D_EMB) e[t] = emb[n * D_EMB + t];
    __syncthreads();
    #pragma unroll
    for (int j = 0; j < 16; j++) {
        int idx = j * 256 + t;                        // f*64 + h, < 4096
        float v = 0.f;
        #pragma unroll
        for (int d = 0; d < D_EMB; d++) v += e[d] * pool[d * 4096 + idx];
        g_nw[n * 4096 + idx] = v;
    }
}

// ================= K1: g_sim = H @ g_A + bias =================
// 512 blocks x 256 threads; block tile 128x128, k-tile 16, thread tile 8x8.
__global__ __launch_bounds__(256) void k1_gemm(const float* __restrict__ H) {
    __shared__ float As[16][128];   // H tile, transposed
    __shared__ float Bs[16][128];   // A tile, natural
    int tid = threadIdx.x;
    int row0 = blockIdx.x << 7;
    int ty = tid >> 4, tx = tid & 15;
    float acc[8][8] = {};
    const float* Hb = H + (size_t)row0 * KDIM;

    for (int kt = 0; kt < KDIM; kt += 16) {
        #pragma unroll
        for (int i = 0; i < 2; i++) {
            int id = tid + i * 256;                   // < 512 float4
            int m = id >> 2, kk = (id & 3) << 2;
            float4 v = *(const float4*)(Hb + (size_t)m * KDIM + kt + kk);
            As[kk + 0][m] = v.x; As[kk + 1][m] = v.y;
            As[kk + 2][m] = v.z; As[kk + 3][m] = v.w;
        }
        #pragma unroll
        for (int i = 0; i < 2; i++) {
            int id = tid + i * 256;
            int k = id >> 5, n4 = (id & 31) << 2;
            *(float4*)&Bs[k][n4] = *(const float4*)(g_A + (kt + k) * CDIM + n4);
        }
        __syncthreads();
        #pragma unroll
        for (int k = 0; k < 16; k++) {
            float4 a0 = *(float4*)&As[k][ty * 8];
            float4 a1 = *(float4*)&As[k][ty * 8 + 4];
            float4 b0 = *(float4*)&Bs[k][tx * 8];
            float4 b1 = *(float4*)&Bs[k][tx * 8 + 4];
            float a[8] = {a0.x,a0.y,a0.z,a0.w,a1.x,a1.y,a1.z,a1.w};
            float b[8] = {b0.x,b0.y,b0.z,b0.w,b1.x,b1.y,b1.z,b1.w};
            #pragma unroll
            for (int i = 0; i < 8; i++)
                #pragma unroll
                for (int j = 0; j < 8; j++) acc[i][j] += a[i] * b[j];
        }
        __syncthreads();
    }
    #pragma unroll
    for (int i = 0; i < 8; i++) {
        size_t r = row0 + ty * 8 + i;
        float* op = g_sim + r * CDIM + tx * 8;
        #pragma unroll
        for (int j = 0; j < 8; j++) op[j] = acc[i][j] + g_bias[tx * 8 + j];
    }
}

// ================= K2: softmax + context + per-node projection =================
// 1024 blocks (one per node n), 8 warps; each warp handles 8 batch rows.
__global__ __launch_bounds__(256) void k2_epi(float* __restrict__ out) {
    __shared__ float snw[64][64];    // node_w[n]
    __shared__ float sLm[64][32];
    __shared__ float sGm[64][32];
    __shared__ float sattn[8][128];
    __shared__ float sfused[8][64];

    int n = blockIdx.x, tid = threadIdx.x;
    int w = tid >> 5, lane = tid & 31;

    // stage node weights + bank means
    {
        const float4* src = (const float4*)(g_nw + (size_t)n * 4096);
        float4* dst = (float4*)&snw[0][0];
        #pragma unroll
        for (int i = 0; i < 4; i++) dst[tid + i * 256] = src[tid + i * 256];
        float* lm = &sLm[0][0]; float* gm = &sGm[0][0];
        for (int i = tid; i < 2048; i += 256) { lm[i] = g_Lm[i]; gm[i] = g_Gm[i]; }
    }
    __syncthreads();

    for (int i = 0; i < 8; i++) {
        int b = i * 8 + w;
        size_t row = (size_t)b * N_NODES + n;
        const float* sp = g_sim + row * CDIM;
        float v0 = sp[lane], v1 = sp[lane + 32];          // local logits
        float v2 = sp[lane + 64], v3 = sp[lane + 96];     // global logits

        // local softmax (64 wide)
        float mx = fmaxf(v0, v1);
        #pragma unroll
        for (int o = 16; o; o >>= 1) mx = fmaxf(mx, __shfl_xor_sync(0xffffffffu, mx, o));
        float e0 = __expf(v0 - mx), e1 = __expf(v1 - mx);
        float s = e0 + e1;
        #pragma unroll
        for (int o = 16; o; o >>= 1) s += __shfl_xor_sync(0xffffffffu, s, o);
        float inv = 1.f / s;
        sattn[w][lane] = e0 * inv; sattn[w][lane + 32] = e1 * inv;

        // global softmax (64 wide)
        mx = fmaxf(v2, v3);
        #pragma unroll
        for (int o = 16; o; o >>= 1) mx = fmaxf(mx, __shfl_xor_sync(0xffffffffu, mx, o));
        float e2 = __expf(v2 - mx), e3 = __expf(v3 - mx);
        s = e2 + e3;
        #pragma unroll
        for (int o = 16; o; o >>= 1) s += __shfl_xor_sync(0xffffffffu, s, o);
        inv = 1.f / s;
        sattn[w][64 + lane] = e2 * inv; sattn[w][96 + lane] = e3 * inv;
        __syncwarp();

        // contexts: lane owns pattern p = lane
        float lctx = 0.f, gctx = 0.f;
        #pragma unroll 8
        for (int m = 0; m < 64; m++) {
            lctx += sattn[w][m]      * sLm[m][lane];
            gctx += sattn[w][64 + m] * sGm[m][lane];
        }
        sfused[w][lane] = lctx; sfused[w][lane + 32] = gctx;
        __syncwarp();

        // out[row][h] = sum_f fused[f] * nw[f][h]; lane covers h=lane, lane+32
        float o0 = 0.f, o1 = 0.f;
        #pragma unroll 8
        for (int f = 0; f < 64; f++) {
            float fv = sfused[w][f];
            o0 += fv * snw[f][lane];
            o1 += fv * snw[f][lane + 32];
        }
        float* op = out + row * HID;
        op[lane] = o0; op[lane + 32] = o1;
        __syncwarp();
    }
}

// ================= launch =================
extern "C" void kernel_launch(void* const* d_in, const int* in_sizes, int n_in,
                              void* d_out, int out_size) {
    const float* H    = (const float*)d_in[0];   // [64,1024,12,64]
    const float* G    = (const float*)d_in[1];   // [64,6,32]
    const float* L    = (const float*)d_in[2];   // [64,12,32]
    const float* Wq   = (const float*)d_in[3];   // [64,32]
    const float* bq   = (const float*)d_in[4];   // [32]
    const float* emb  = (const float*)d_in[5];   // [1024,16]
    const float* pool = (const float*)d_in[6];   // [16,64,64]
    float* out = (float*)d_out;                  // [64,1024,64]

    pA_kernel  <<<384, 256>>>(G, L, Wq);
    pBias_kernel<<<1, 128>>>(G, L, bq);
    pMean_kernel<<<8, 256>>>(G, L);
    pNw_kernel <<<N_NODES, 256>>>(emb, pool);
    k1_gemm    <<<ROWS / 128, 256>>>(H);
    k2_epi     <<<N_NODES, 256>>>(out);
}

// round 5
// speedup vs baseline: 2.0299x; 2.0299x over previous
#include <cuda_runtime.h>
#include <cuda_bf16.h>
#include <cstdint>

// ---------------- problem constants ----------------
#define B_BATCH 64
#define N_NODES 1024
#define S_LOC   12
#define HID     64
#define PAT     32
#define M_GLB   64
#define S_GLB   6
#define M_LOC   64
#define D_EMB   16
#define KDIM    768           // S_LOC * HID
#define CDIM    128           // M_LOC + M_GLB
#define ROWS    65536         // B_BATCH * N_NODES
#define NCHUNK  12            // K chunks of 64

// tcgen05 is an arch-SPECIFIC feature: only emit its PTX in the sm_103a
// (or sm_100a) device pass. The harness also builds a generic compute_103
// PTX where these instructions are illegal; that pass gets a scalar fallback.
#if defined(__CUDA_ARCH_FEAT_SM103_ALL) || defined(__CUDA_ARCH_FEAT_SM100_ALL) || \
    (defined(__CUDA_ARCH_SPECIFIC__) && (__CUDA_ARCH_SPECIFIC__ == 1030 || __CUDA_ARCH_SPECIFIC__ == 1000))
#define HAS_TCGEN05 1
#else
#define HAS_TCGEN05 0
#endif

// ---------------- static device scratch (no allocations allowed) ----------------
__device__ __align__(16) float g_A[KDIM * CDIM];           // folded weights  [768][128]
__device__ __align__(16) float g_bias[CDIM];
__device__ __align__(16) float g_Lm[M_LOC * PAT];
__device__ __align__(16) float g_Gm[M_GLB * PAT];
__device__ __align__(16) float g_nw[N_NODES * 64 * HID];   // [1024][64][64]
__device__ __align__(16) float g_sim[(size_t)ROWS * CDIM]; // logits [65536][128]
// pre-swizzled bf16 B operand (hi/lo), [chunk][128 n-rows][128 bytes]
__device__ __align__(16) unsigned char g_Bhi[NCHUNK * 128 * 128];
__device__ __align__(16) unsigned char g_Blo[NCHUNK * 128 * 128];

// ---------------- helpers legal on all targets ----------------
__device__ __forceinline__ uint32_t su32(const void* p) {
    uint32_t a;
    asm("{ .reg .u64 t; cvta.to.shared.u64 t, %1; cvt.u32.u64 %0, t; }" : "=r"(a) : "l"(p));
    return a;
}
// pack {low=bf16(x0), high=bf16(x1)}
__device__ __forceinline__ uint32_t bf16pack(float x0, float x1) {
    uint32_t r;
    asm("cvt.rn.bf16x2.f32 %0, %1, %2;" : "=r"(r) : "f"(x1), "f"(x0));
    return r;
}
// split pair (x0,x1) -> hi bf16x2 + lo bf16x2 (residual)
__device__ __forceinline__ void bf16split(float x0, float x1, uint32_t& hi, uint32_t& lo) {
    hi = bf16pack(x0, x1);
    float h0 = __uint_as_float(hi << 16);
    float h1 = __uint_as_float(hi & 0xffff0000u);
    lo = bf16pack(x0 - h0, x1 - h1);
}

#if HAS_TCGEN05
__device__ __forceinline__ uint32_t elect1() {
    uint32_t r;
    asm volatile("{ .reg .pred p; elect.sync _|p, 0xFFFFFFFF; selp.b32 %0, 1, 0, p; }" : "=r"(r));
    return r;
}
__device__ __forceinline__ uint64_t mkdesc(uint32_t saddr) {
    // SW128 K-major: layout=2, version=1, SBO=64, LBO=1
    return 0x4000404000010000ULL | ((uint64_t)(saddr >> 4) & 0x3FFF);
}
__device__ __forceinline__ void mma_f16_ss(uint32_t d, uint64_t ad, uint64_t bd,
                                           uint32_t idesc, uint32_t en) {
    asm volatile(
        "{\n\t.reg .pred p;\n\tsetp.ne.u32 p, %4, 0;\n\t"
        "tcgen05.mma.cta_group::1.kind::f16 [%0], %1, %2, %3, {%5, %5, %5, %5}, p;\n\t}"
        :: "r"(d), "l"(ad), "l"(bd), "r"(idesc), "r"(en), "r"(0u) : "memory");
}
#define MBAR_INIT(a, n) asm volatile("mbarrier.init.shared.b64 [%0], %1;" :: "r"(a), "r"(n) : "memory")
#define MBAR_WAITP(addr, par) do {                                                      \
    uint32_t _m = (addr), _p = (par), _d;                                               \
    asm volatile("{\n\t.reg .pred p;\n\t"                                               \
        "mbarrier.try_wait.parity.acquire.cta.shared::cta.b64 p, [%1], %2;\n\t"         \
        "selp.b32 %0, 1, 0, p;\n\t}" : "=r"(_d) : "r"(_m), "r"(_p) : "memory");         \
    if (!_d) {                                                                          \
        asm volatile("{\n\t.reg .pred P1;\n\tWL_%=:\n\t"                                \
            "mbarrier.try_wait.parity.acquire.cta.shared::cta.b64 P1, [%0], %1, 0x989680;\n\t" \
            "@P1 bra.uni WD_%=;\n\tbra.uni WL_%=;\n\tWD_%=:\n\t}"                       \
            :: "r"(_m), "r"(_p) : "memory");                                            \
    }                                                                                   \
} while (0)
#define TC_COMMIT(a) asm volatile("tcgen05.commit.cta_group::1.mbarrier::arrive::one.shared::cluster.b64 [%0];" :: "r"(a) : "memory")
#define TC_WAITLD()  asm volatile("tcgen05.wait::ld.sync.aligned;" ::: "memory")
#define LDTM32(r, a) asm volatile(                                                      \
    "tcgen05.ld.sync.aligned.32x32b.x32.b32 "                                           \
    "{%0, %1, %2, %3, %4, %5, %6, %7, %8, %9, %10, %11, %12, %13, %14, %15, "           \
    " %16, %17, %18, %19, %20, %21, %22, %23, %24, %25, %26, %27, %28, %29, %30, %31}, [%32];" \
    : "=r"((r)[0]), "=r"((r)[1]), "=r"((r)[2]), "=r"((r)[3]),                           \
      "=r"((r)[4]), "=r"((r)[5]), "=r"((r)[6]), "=r"((r)[7]),                           \
      "=r"((r)[8]), "=r"((r)[9]), "=r"((r)[10]), "=r"((r)[11]),                         \
      "=r"((r)[12]), "=r"((r)[13]), "=r"((r)[14]), "=r"((r)[15]),                       \
      "=r"((r)[16]), "=r"((r)[17]), "=r"((r)[18]), "=r"((r)[19]),                       \
      "=r"((r)[20]), "=r"((r)[21]), "=r"((r)[22]), "=r"((r)[23]),                       \
      "=r"((r)[24]), "=r"((r)[25]), "=r"((r)[26]), "=r"((r)[27]),                       \
      "=r"((r)[28]), "=r"((r)[29]), "=r"((r)[30]), "=r"((r)[31])                        \
    : "r"(a))
// idesc: fp32 accum, bf16 x bf16, M=128, N=128, K-major both
#define IDESC_BF16 0x8200490u
#endif  // HAS_TCGEN05

// ================= P1: A[k][c] = folded bank weights =================
__global__ void pA_kernel(const float* __restrict__ G, const float* __restrict__ L,
                          const float* __restrict__ Wq) {
    int t = blockIdx.x * 256 + threadIdx.x;          // < 98304 = 768*128
    int k = t >> 7, c = t & 127;
    int s = k >> 6, h = k & 63;
    const float* wp = Wq + h * PAT;
    float v = 0.f;
    if (c < 64) {
        const float* lp = L + c * (S_LOC * PAT) + s * PAT;
        #pragma unroll
        for (int p = 0; p < PAT; p++) v += wp[p] * lp[p];
    } else {
        const float* gp = G + (c - 64) * (S_GLB * PAT) + (s >> 1) * PAT;
        #pragma unroll
        for (int p = 0; p < PAT; p++) v += wp[p] * gp[p];
        v *= 0.5f;
    }
    g_A[k * CDIM + c] = v;
}

// ================= P2: bias[c] =================
__global__ void pBias_kernel(const float* __restrict__ G, const float* __restrict__ L,
                             const float* __restrict__ bq) {
    int c = threadIdx.x;
    float v = 0.f;
    if (c < 64) {
        for (int s = 0; s < S_LOC; s++)
            #pragma unroll
            for (int p = 0; p < PAT; p++) v += bq[p] * L[c * (S_LOC * PAT) + s * PAT + p];
    } else {
        for (int s = 0; s < S_GLB; s++)
            #pragma unroll
            for (int p = 0; p < PAT; p++) v += bq[p] * G[(c - 64) * (S_GLB * PAT) + s * PAT + p];
    }
    g_bias[c] = v;
}

// ================= P3: bank means =================
__global__ void pMean_kernel(const float* __restrict__ G, const float* __restrict__ L) {
    int idx = blockIdx.x * 256 + threadIdx.x;
    if (idx >= 2048) return;
    int m = idx >> 5, p = idx & 31;
    float lm = 0.f, gm = 0.f;
    for (int s = 0; s < S_LOC; s++) lm += L[m * (S_LOC * PAT) + s * PAT + p];
    for (int s = 0; s < S_GLB; s++) gm += G[m * (S_GLB * PAT) + s * PAT + p];
    g_Lm[idx] = lm * (1.f / 12.f);
    g_Gm[idx] = gm * (1.f / 6.f);
}

// ================= P4: pre-swizzled bf16 hi/lo split of B = g_A^T =================
__global__ void pBsw_kernel() {
    int t = blockIdx.x * 256 + threadIdx.x;          // < 12288
    int ci = t >> 10;                                // chunk
    int n  = (t >> 3) & 127;                         // B row (N dim)
    int kq = t & 7;                                  // 8-element group in 64-k chunk
    uint32_t hi[4], lo[4];
    #pragma unroll
    for (int p = 0; p < 4; p++) {
        int k0 = ci * 64 + kq * 8 + 2 * p;
        float x0 = g_A[(k0 + 0) * CDIM + n];
        float x1 = g_A[(k0 + 1) * CDIM + n];
        bf16split(x0, x1, hi[p], lo[p]);
    }
    int off = n * 128 + kq * 16;
    int swo = off ^ ((off >> 3) & 0x70);
    *(uint4*)(g_Bhi + ci * 16384 + swo) = make_uint4(hi[0], hi[1], hi[2], hi[3]);
    *(uint4*)(g_Blo + ci * 16384 + swo) = make_uint4(lo[0], lo[1], lo[2], lo[3]);
}

// ================= K1: tcgen05 bf16x3 GEMM: g_sim = H @ g_A + bias =================
// smem: [0..4) tmem ptr, [16..32) 2 mbarriers, [64..576) bias, [1024..) 2 x 64KB stages
// stage: Ahi(16K) Alo(16K) Bhi(16K) Blo(16K)
#define K1_SMEM (1024 + 2 * 65536)
__global__ __launch_bounds__(256, 1) void k1_tc(const float* __restrict__ H) {
#if HAS_TCGEN05
    extern __shared__ __align__(1024) char smem[];
    const int tid = threadIdx.x, w = tid >> 5, lane = tid & 31;
    const int row0 = blockIdx.x << 7;
    uint32_t sb = su32(smem);

    if (w == 0) {
        asm volatile("tcgen05.alloc.cta_group::1.sync.aligned.shared::cta.b32 [%0], %1;"
                     :: "r"(sb), "r"(128u) : "memory");
    } else {
        asm volatile("tcgen05.relinquish_alloc_permit.cta_group::1.sync.aligned;");
    }
    if (tid == 0) { MBAR_INIT(sb + 16, 1); MBAR_INIT(sb + 24, 1); }
    float* sbias = (float*)(smem + 64);
    if (tid < 128) sbias[tid] = g_bias[tid];
    __syncthreads();
    uint32_t tmem;
    asm("ld.shared.b32 %0, [%1];" : "=r"(tmem) : "r"(sb));

    for (int c = 0; c < NCHUNK; c++) {
        const int st = c & 1;
        char* buf = smem + 1024 + st * 65536;
        const uint32_t bufb = sb + 1024 + st * 65536;
        const int u = c >> 1;
        if (u >= 1) MBAR_WAITP(sb + 16 + st * 8, (uint32_t)((u - 1) & 1));

        // stage B (pre-swizzled, straight copies)
        {
            const uint4* bh = (const uint4*)g_Bhi + c * 1024;
            const uint4* bl = (const uint4*)g_Blo + c * 1024;
            uint4* dh = (uint4*)(buf + 32768);
            uint4* dl = (uint4*)(buf + 49152);
            #pragma unroll
            for (int i = 0; i < 4; i++) {
                dh[i * 256 + tid] = bh[i * 256 + tid];
                dl[i * 256 + tid] = bl[i * 256 + tid];
            }
        }
        // stage A: load H fp32, split hi/lo, swizzled STS
        #pragma unroll
        for (int it = 0; it < 4; it++) {
            int task = it * 256 + tid;
            int r = task >> 3, kq = task & 7;
            const float* hp = H + (size_t)(row0 + r) * KDIM + c * 64 + kq * 8;
            float4 u0 = *(const float4*)hp;
            float4 u1 = *(const float4*)(hp + 4);
            uint32_t hi[4], lo[4];
            bf16split(u0.x, u0.y, hi[0], lo[0]);
            bf16split(u0.z, u0.w, hi[1], lo[1]);
            bf16split(u1.x, u1.y, hi[2], lo[2]);
            bf16split(u1.z, u1.w, hi[3], lo[3]);
            int off = r * 128 + kq * 16;
            int swo = off ^ ((off >> 3) & 0x70);
            *(uint4*)(buf + swo)         = make_uint4(hi[0], hi[1], hi[2], hi[3]);
            *(uint4*)(buf + 16384 + swo) = make_uint4(lo[0], lo[1], lo[2], lo[3]);
        }
        asm volatile("fence.proxy.async.shared::cta;" ::: "memory");
        __syncthreads();

        if (w == 0 && elect1()) {
            uint64_t ah = mkdesc(bufb);
            uint64_t al = mkdesc(bufb + 16384);
            uint64_t bh = mkdesc(bufb + 32768);
            uint64_t bl = mkdesc(bufb + 49152);
            #pragma unroll
            for (int ks = 0; ks < 4; ks++) {
                uint32_t en0 = (c == 0 && ks == 0) ? 0u : 1u;
                mma_f16_ss(tmem, ah + 2 * ks, bh + 2 * ks, IDESC_BF16, en0);
                mma_f16_ss(tmem, ah + 2 * ks, bl + 2 * ks, IDESC_BF16, 1u);
                mma_f16_ss(tmem, al + 2 * ks, bh + 2 * ks, IDESC_BF16, 1u);
            }
            TC_COMMIT(sb + 16 + st * 8);
        }
    }

    // stage-1 barrier got 6 commits; after the 6th its phase is 1.
    MBAR_WAITP(sb + 24, 1u);
    asm volatile("tcgen05.fence::after_thread_sync;" ::: "memory");

    if (w < 4) {
        #pragma unroll
        for (int base = 0; base < 128; base += 32) {
            uint32_t dr[32];
            LDTM32(dr, tmem + base);
            TC_WAITLD();
            float* op = g_sim + (size_t)(row0 + w * 32 + lane) * CDIM + base;
            #pragma unroll
            for (int j = 0; j < 32; j += 4) {
                float4 o;
                o.x = __uint_as_float(dr[j + 0]) + sbias[base + j + 0];
                o.y = __uint_as_float(dr[j + 1]) + sbias[base + j + 1];
                o.z = __uint_as_float(dr[j + 2]) + sbias[base + j + 2];
                o.w = __uint_as_float(dr[j + 3]) + sbias[base + j + 3];
                *(float4*)(op + j) = o;
            }
        }
        asm volatile("tcgen05.fence::before_thread_sync;" ::: "memory");
    }
    __syncthreads();
    if (w == 0) {
        asm volatile("tcgen05.dealloc.cta_group::1.sync.aligned.b32 %0, %1;"
                     :: "r"(tmem), "r"(128u));
    }
#else
    // Generic-arch fallback (never executed on sm_103a; keeps compute_103 PTX legal
    // and correct). Classic 128x128 tile, 8x8 micro-tile, fp32.
    extern __shared__ __align__(1024) char smem[];
    float (*As)[128] = (float(*)[128])smem;            // [16][128]
    float (*Bs)[128] = (float(*)[128])(smem + 8192);   // [16][128]
    int tid = threadIdx.x;
    int row0 = blockIdx.x << 7;
    int ty = tid >> 4, tx = tid & 15;
    float acc[8][8] = {};
    const float* Hb = H + (size_t)row0 * KDIM;
    for (int kt = 0; kt < KDIM; kt += 16) {
        #pragma unroll
        for (int i = 0; i < 2; i++) {
            int id = tid + i * 256;
            int m = id >> 2, kk = (id & 3) << 2;
            float4 v = *(const float4*)(Hb + (size_t)m * KDIM + kt + kk);
            As[kk + 0][m] = v.x; As[kk + 1][m] = v.y;
            As[kk + 2][m] = v.z; As[kk + 3][m] = v.w;
        }
        #pragma unroll
        for (int i = 0; i < 2; i++) {
            int id = tid + i * 256;
            int k = id >> 5, n4 = (id & 31) << 2;
            *(float4*)&Bs[k][n4] = *(const float4*)(g_A + (kt + k) * CDIM + n4);
        }
        __syncthreads();
        #pragma unroll
        for (int k = 0; k < 16; k++) {
            float a[8], b[8];
            #pragma unroll
            for (int i = 0; i < 8; i++) a[i] = As[k][ty * 8 + i];
            #pragma unroll
            for (int j = 0; j < 8; j++) b[j] = Bs[k][tx * 8 + j];
            #pragma unroll
            for (int i = 0; i < 8; i++)
                #pragma unroll
                for (int j = 0; j < 8; j++) acc[i][j] += a[i] * b[j];
        }
        __syncthreads();
    }
    #pragma unroll
    for (int i = 0; i < 8; i++) {
        size_t r = row0 + ty * 8 + i;
        float* op = g_sim + r * CDIM + tx * 8;
        #pragma unroll
        for (int j = 0; j < 8; j++) op[j] = acc[i][j] + g_bias[tx * 8 + j];
    }
#endif
}

// ================= P5: node_w = emb @ pool (4 nodes/block, float4 ILP) =================
__global__ __launch_bounds__(256) void pNw_kernel(const float* __restrict__ emb,
                                                  const float* __restrict__ pool) {
    __shared__ float se[4][16];
    int n0 = blockIdx.x << 2, tid = threadIdx.x;
    if (tid < 64) se[tid >> 4][tid & 15] = emb[(n0 + (tid >> 4)) * D_EMB + (tid & 15)];
    __syncthreads();
    float e0[16], e1[16], e2[16], e3[16];
    #pragma unroll
    for (int d = 0; d < 16; d++) {
        e0[d] = se[0][d]; e1[d] = se[1][d]; e2[d] = se[2][d]; e3[d] = se[3][d];
    }
    const float4* p4 = (const float4*)pool;
    #pragma unroll
    for (int j = 0; j < 4; j++) {
        int o = j * 256 + tid;
        float4 a0 = {0, 0, 0, 0}, a1 = a0, a2 = a0, a3 = a0;
        #pragma unroll
        for (int d = 0; d < 16; d++) {
            float4 pv = p4[d * 1024 + o];
            a0.x += e0[d] * pv.x; a0.y += e0[d] * pv.y; a0.z += e0[d] * pv.z; a0.w += e0[d] * pv.w;
            a1.x += e1[d] * pv.x; a1.y += e1[d] * pv.y; a1.z += e1[d] * pv.z; a1.w += e1[d] * pv.w;
            a2.x += e2[d] * pv.x; a2.y += e2[d] * pv.y; a2.z += e2[d] * pv.z; a2.w += e2[d] * pv.w;
            a3.x += e3[d] * pv.x; a3.y += e3[d] * pv.y; a3.z += e3[d] * pv.z; a3.w += e3[d] * pv.w;
        }
        float4* nw4 = (float4*)g_nw;
        nw4[(size_t)(n0 + 0) * 1024 + o] = a0;
        nw4[(size_t)(n0 + 1) * 1024 + o] = a1;
        nw4[(size_t)(n0 + 2) * 1024 + o] = a2;
        nw4[(size_t)(n0 + 3) * 1024 + o] = a3;
    }
}

// ================= K2: softmax + context + per-node projection =================
__global__ __launch_bounds__(256) void k2_epi(float* __restrict__ out) {
    __shared__ float snw[64][64];
    __shared__ float sLm[64][32];
    __shared__ float sGm[64][32];
    __shared__ float sattn[8][128];
    __shared__ float sfused[8][64];

    int n = blockIdx.x, tid = threadIdx.x;
    int w = tid >> 5, lane = tid & 31;

    {
        const float4* src = (const float4*)(g_nw + (size_t)n * 4096);
        float4* dst = (float4*)&snw[0][0];
        #pragma unroll
        for (int i = 0; i < 4; i++) dst[tid + i * 256] = src[tid + i * 256];
        float* lm = &sLm[0][0]; float* gm = &sGm[0][0];
        for (int i = tid; i < 2048; i += 256) { lm[i] = g_Lm[i]; gm[i] = g_Gm[i]; }
    }
    __syncthreads();

    for (int i = 0; i < 8; i++) {
        int b = i * 8 + w;
        size_t row = (size_t)b * N_NODES + n;
        const float* sp = g_sim + row * CDIM;
        float v0 = sp[lane], v1 = sp[lane + 32];
        float v2 = sp[lane + 64], v3 = sp[lane + 96];

        float mx = fmaxf(v0, v1);
        #pragma unroll
        for (int o = 16; o; o >>= 1) mx = fmaxf(mx, __shfl_xor_sync(0xffffffffu, mx, o));
        float e0 = __expf(v0 - mx), e1 = __expf(v1 - mx);
        float s = e0 + e1;
        #pragma unroll
        for (int o = 16; o; o >>= 1) s += __shfl_xor_sync(0xffffffffu, s, o);
        float inv = 1.f / s;
        sattn[w][lane] = e0 * inv; sattn[w][lane + 32] = e1 * inv;

        mx = fmaxf(v2, v3);
        #pragma unroll
        for (int o = 16; o; o >>= 1) mx = fmaxf(mx, __shfl_xor_sync(0xffffffffu, mx, o));
        float e2 = __expf(v2 - mx), e3 = __expf(v3 - mx);
        s = e2 + e3;
        #pragma unroll
        for (int o = 16; o; o >>= 1) s += __shfl_xor_sync(0xffffffffu, s, o);
        inv = 1.f / s;
        sattn[w][64 + lane] = e2 * inv; sattn[w][96 + lane] = e3 * inv;
        __syncwarp();

        float lctx = 0.f, gctx = 0.f;
        #pragma unroll 8
        for (int m = 0; m < 64; m++) {
            lctx += sattn[w][m]      * sLm[m][lane];
            gctx += sattn[w][64 + m] * sGm[m][lane];
        }
        sfused[w][lane] = lctx; sfused[w][lane + 32] = gctx;
        __syncwarp();

        float o0 = 0.f, o1 = 0.f;
        #pragma unroll 8
        for (int f = 0; f < 64; f++) {
            float fv = sfused[w][f];
            o0 += fv * snw[f][lane];
            o1 += fv * snw[f][lane + 32];
        }
        float* op = out + row * HID;
        op[lane] = o0; op[lane + 32] = o1;
        __syncwarp();
    }
}

// ================= launch =================
extern "C" void kernel_launch(void* const* d_in, const int* in_sizes, int n_in,
                              void* d_out, int out_size) {
    const float* H    = (const float*)d_in[0];   // [64,1024,12,64]
    const float* G    = (const float*)d_in[1];   // [64,6,32]
    const float* L    = (const float*)d_in[2];   // [64,12,32]
    const float* Wq   = (const float*)d_in[3];   // [64,32]
    const float* bq   = (const float*)d_in[4];   // [32]
    const float* emb  = (const float*)d_in[5];   // [1024,16]
    const float* pool = (const float*)d_in[6];   // [16,64,64]
    float* out = (float*)d_out;                  // [64,1024,64]

    static bool attr_done = false;
    if (!attr_done) {
        cudaFuncSetAttribute(k1_tc, cudaFuncAttributeMaxDynamicSharedMemorySize, K1_SMEM);
        attr_done = true;
    }

    pA_kernel   <<<384, 256>>>(G, L, Wq);
    pBias_kernel<<<1, 128>>>(G, L, bq);
    pMean_kernel<<<8, 256>>>(G, L);
    pBsw_kernel <<<48, 256>>>();
    k1_tc       <<<ROWS / 128, 256, K1_SMEM>>>(H);
    pNw_kernel  <<<256, 256>>>(emb, pool);
    k2_epi      <<<N_NODES, 256>>>(out);
}

// round 6
// speedup vs baseline: 2.1627x; 1.0655x over previous
#include <cuda_runtime.h>
#include <cuda_bf16.h>
#include <cstdint>

// ---------------- problem constants ----------------
#define B_BATCH 64
#define N_NODES 1024
#define S_LOC   12
#define HID     64
#define PAT     32
#define M_GLB   64
#define S_GLB   6
#define M_LOC   64
#define D_EMB   16
#define KDIM    768           // S_LOC * HID
#define CDIM    128           // M_LOC + M_GLB
#define ROWS    65536         // B_BATCH * N_NODES
#define NCHUNK  12            // K chunks of 64

// tcgen05 is arch-SPECIFIC: only emit its PTX in the sm_103a/sm_100a pass.
#if defined(__CUDA_ARCH_FEAT_SM103_ALL) || defined(__CUDA_ARCH_FEAT_SM100_ALL) || \
    (defined(__CUDA_ARCH_SPECIFIC__) && (__CUDA_ARCH_SPECIFIC__ == 1030 || __CUDA_ARCH_SPECIFIC__ == 1000))
#define HAS_TCGEN05 1
#else
#define HAS_TCGEN05 0
#endif

// ---------------- static device scratch ----------------
__device__ __align__(16) float g_A[KDIM * CDIM];           // folded weights  [768][128]
__device__ __align__(16) float g_bias[CDIM];
__device__ __align__(16) float g_Lm[M_LOC * PAT];
__device__ __align__(16) float g_Gm[M_GLB * PAT];
__device__ __align__(16) float g_nw[N_NODES * 64 * HID];   // [1024][64][64]
__device__ __align__(16) float g_sim[(size_t)ROWS * CDIM]; // logits [65536][128]
// pre-swizzled bf16 B operand (hi/lo), [chunk][128 n-rows][128 bytes]
__device__ __align__(16) unsigned char g_Bhi[NCHUNK * 128 * 128];
__device__ __align__(16) unsigned char g_Blo[NCHUNK * 128 * 128];

// ---------------- helpers legal on all targets ----------------
__device__ __forceinline__ uint32_t su32(const void* p) {
    uint32_t a;
    asm("{ .reg .u64 t; cvta.to.shared.u64 t, %1; cvt.u32.u64 %0, t; }" : "=r"(a) : "l"(p));
    return a;
}
__device__ __forceinline__ uint32_t bf16pack(float x0, float x1) {
    uint32_t r;
    asm("cvt.rn.bf16x2.f32 %0, %1, %2;" : "=r"(r) : "f"(x1), "f"(x0));
    return r;
}
__device__ __forceinline__ void bf16split(float x0, float x1, uint32_t& hi, uint32_t& lo) {
    hi = bf16pack(x0, x1);
    float h0 = __uint_as_float(hi << 16);
    float h1 = __uint_as_float(hi & 0xffff0000u);
    lo = bf16pack(x0 - h0, x1 - h1);
}
__device__ __forceinline__ void cp16(uint32_t saddr, const void* gaddr) {
    asm volatile("cp.async.cg.shared.global [%0], [%1], 16;" :: "r"(saddr), "l"(gaddr) : "memory");
}

#if HAS_TCGEN05
__device__ __forceinline__ uint32_t elect1() {
    uint32_t r;
    asm volatile("{ .reg .pred p; elect.sync _|p, 0xFFFFFFFF; selp.b32 %0, 1, 0, p; }" : "=r"(r));
    return r;
}
__device__ __forceinline__ uint64_t mkdesc(uint32_t saddr) {
    // SW128 K-major: layout=2, version=1, SBO=64, LBO=1
    return 0x4000404000010000ULL | ((uint64_t)(saddr >> 4) & 0x3FFF);
}
__device__ __forceinline__ void mma_f16_ss(uint32_t d, uint64_t ad, uint64_t bd,
                                           uint32_t idesc, uint32_t en) {
    asm volatile(
        "{\n\t.reg .pred p;\n\tsetp.ne.u32 p, %4, 0;\n\t"
        "tcgen05.mma.cta_group::1.kind::f16 [%0], %1, %2, %3, {%5, %5, %5, %5}, p;\n\t}"
        :: "r"(d), "l"(ad), "l"(bd), "r"(idesc), "r"(en), "r"(0u) : "memory");
}
#define MBAR_INIT(a, n) asm volatile("mbarrier.init.shared.b64 [%0], %1;" :: "r"(a), "r"(n) : "memory")
#define MBAR_WAITP(addr, par) do {                                                      \
    uint32_t _m = (addr), _p = (par), _d;                                               \
    asm volatile("{\n\t.reg .pred p;\n\t"                                               \
        "mbarrier.try_wait.parity.acquire.cta.shared::cta.b64 p, [%1], %2;\n\t"         \
        "selp.b32 %0, 1, 0, p;\n\t}" : "=r"(_d) : "r"(_m), "r"(_p) : "memory");         \
    if (!_d) {                                                                          \
        asm volatile("{\n\t.reg .pred P1;\n\tWL_%=:\n\t"                                \
            "mbarrier.try_wait.parity.acquire.cta.shared::cta.b64 P1, [%0], %1, 0x989680;\n\t" \
            "@P1 bra.uni WD_%=;\n\tbra.uni WL_%=;\n\tWD_%=:\n\t}"                       \
            :: "r"(_m), "r"(_p) : "memory");                                            \
    }                                                                                   \
} while (0)
#define TC_COMMIT(a) asm volatile("tcgen05.commit.cta_group::1.mbarrier::arrive::one.shared::cluster.b64 [%0];" :: "r"(a) : "memory")
#define TC_WAITLD()  asm volatile("tcgen05.wait::ld.sync.aligned;" ::: "memory")
#define LDTM32(r, a) asm volatile(                                                      \
    "tcgen05.ld.sync.aligned.32x32b.x32.b32 "                                           \
    "{%0, %1, %2, %3, %4, %5, %6, %7, %8, %9, %10, %11, %12, %13, %14, %15, "           \
    " %16, %17, %18, %19, %20, %21, %22, %23, %24, %25, %26, %27, %28, %29, %30, %31}, [%32];" \
    : "=r"((r)[0]), "=r"((r)[1]), "=r"((r)[2]), "=r"((r)[3]),                           \
      "=r"((r)[4]), "=r"((r)[5]), "=r"((r)[6]), "=r"((r)[7]),                           \
      "=r"((r)[8]), "=r"((r)[9]), "=r"((r)[10]), "=r"((r)[11]),                         \
      "=r"((r)[12]), "=r"((r)[13]), "=r"((r)[14]), "=r"((r)[15]),                       \
      "=r"((r)[16]), "=r"((r)[17]), "=r"((r)[18]), "=r"((r)[19]),                       \
      "=r"((r)[20]), "=r"((r)[21]), "=r"((r)[22]), "=r"((r)[23]),                       \
      "=r"((r)[24]), "=r"((r)[25]), "=r"((r)[26]), "=r"((r)[27]),                       \
      "=r"((r)[28]), "=r"((r)[29]), "=r"((r)[30]), "=r"((r)[31])                        \
    : "r"(a))
// idesc: fp32 accum, bf16 x bf16, M=128, N=128, K-major both
#define IDESC_BF16 0x8200490u
#endif  // HAS_TCGEN05

// ================= P1: A[k][c] = folded bank weights (coalesced rewrite) =================
// grid = 128 (one block per output column c); block = 256.
__global__ __launch_bounds__(256) void pA_kernel(const float* __restrict__ G,
                                                 const float* __restrict__ L,
                                                 const float* __restrict__ Wq) {
    __shared__ float sBank[S_LOC * PAT];      // 384 floats (L row) or 192 (G row)
    __shared__ float sWq[HID][PAT + 1];       // padded: lane stride 132B, conflict-free
    int c = blockIdx.x, tid = threadIdx.x;

    // stage Wq (coalesced)
    #pragma unroll
    for (int i = tid; i < HID * PAT; i += 256) sWq[i >> 5][i & 31] = Wq[i];
    // stage bank row (coalesced)
    if (c < 64) {
        if (tid < S_LOC * PAT) sBank[tid] = L[c * (S_LOC * PAT) + tid];
        if (tid + 256 < S_LOC * PAT) sBank[tid + 256] = L[c * (S_LOC * PAT) + tid + 256];
    } else {
        if (tid < S_GLB * PAT) sBank[tid] = G[(c - 64) * (S_GLB * PAT) + tid];
    }
    __syncthreads();

    float scale = (c < 64) ? 1.0f : 0.5f;
    #pragma unroll
    for (int j = 0; j < 3; j++) {
        int k = j * 256 + tid;                // < 768
        int s = k >> 6, h = k & 63;
        int base = (c < 64) ? s * PAT : (s >> 1) * PAT;
        float v = 0.f;
        #pragma unroll
        for (int p = 0; p < PAT; p++) v += sWq[h][p] * sBank[base + p];
        g_A[k * CDIM + c] = v * scale;
    }
}

// ================= P2: bias[c] =================
__global__ void pBias_kernel(const float* __restrict__ G, const float* __restrict__ L,
                             const float* __restrict__ bq) {
    int c = threadIdx.x;
    float v = 0.f;
    if (c < 64) {
        for (int s = 0; s < S_LOC; s++)
            #pragma unroll
            for (int p = 0; p < PAT; p++) v += bq[p] * L[c * (S_LOC * PAT) + s * PAT + p];
    } else {
        for (int s = 0; s < S_GLB; s++)
            #pragma unroll
            for (int p = 0; p < PAT; p++) v += bq[p] * G[(c - 64) * (S_GLB * PAT) + s * PAT + p];
    }
    g_bias[c] = v;
}

// ================= P3: bank means =================
__global__ void pMean_kernel(const float* __restrict__ G, const float* __restrict__ L) {
    int idx = blockIdx.x * 256 + threadIdx.x;
    if (idx >= 2048) return;
    int m = idx >> 5, p = idx & 31;
    float lm = 0.f, gm = 0.f;
    for (int s = 0; s < S_LOC; s++) lm += L[m * (S_LOC * PAT) + s * PAT + p];
    for (int s = 0; s < S_GLB; s++) gm += G[m * (S_GLB * PAT) + s * PAT + p];
    g_Lm[idx] = lm * (1.f / 12.f);
    g_Gm[idx] = gm * (1.f / 6.f);
}

// ================= P4: pre-swizzled bf16 hi/lo split of B = g_A^T (coalesced) =================
// lanes map to n (fastest) so g_A reads coalesce.
__global__ void pBsw_kernel() {
    int t = blockIdx.x * 256 + threadIdx.x;          // < 12288
    int ci = t >> 10;                                // chunk
    int kq = (t >> 7) & 7;                           // 8-element k-group
    int n  = t & 127;                                // B row (N dim) — lane-fastest
    uint32_t hi[4], lo[4];
    #pragma unroll
    for (int p = 0; p < 4; p++) {
        int k0 = ci * 64 + kq * 8 + 2 * p;
        float x0 = g_A[(k0 + 0) * CDIM + n];
        float x1 = g_A[(k0 + 1) * CDIM + n];
        bf16split(x0, x1, hi[p], lo[p]);
    }
    int off = n * 128 + kq * 16;
    int swo = off ^ ((off >> 3) & 0x70);
    *(uint4*)(g_Bhi + ci * 16384 + swo) = make_uint4(hi[0], hi[1], hi[2], hi[3]);
    *(uint4*)(g_Blo + ci * 16384 + swo) = make_uint4(lo[0], lo[1], lo[2], lo[3]);
}

// ================= K1: tcgen05 bf16x3 GEMM: g_sim = H @ g_A + bias =================
// smem: [0..4) tmem ptr, [16..32) 2 mbarriers, [64..576) bias, [1024..) 2 x 64KB stages
// stage: Ahi(16K) Alo(16K) Bhi(16K) Blo(16K)
#define K1_SMEM (1024 + 2 * 65536)
__global__ __launch_bounds__(256, 1) void k1_tc(const float* __restrict__ H) {
#if HAS_TCGEN05
    extern __shared__ __align__(1024) char smem[];
    const int tid = threadIdx.x, w = tid >> 5, lane = tid & 31;
    const int row0 = blockIdx.x << 7;
    uint32_t sb = su32(smem);

    if (w == 0) {
        asm volatile("tcgen05.alloc.cta_group::1.sync.aligned.shared::cta.b32 [%0], %1;"
                     :: "r"(sb), "r"(128u) : "memory");
    } else {
        asm volatile("tcgen05.relinquish_alloc_permit.cta_group::1.sync.aligned;");
    }
    if (tid == 0) { MBAR_INIT(sb + 16, 1); MBAR_INIT(sb + 24, 1); }
    float* sbias = (float*)(smem + 64);
    if (tid < 128) sbias[tid] = g_bias[tid];
    __syncthreads();
    uint32_t tmem;
    asm("ld.shared.b32 %0, [%1];" : "=r"(tmem) : "r"(sb));

    for (int c = 0; c < NCHUNK; c++) {
        const int st = c & 1;
        char* buf = smem + 1024 + st * 65536;
        const uint32_t bufb = sb + 1024 + st * 65536;
        const int u = c >> 1;
        if (u >= 1) MBAR_WAITP(sb + 16 + st * 8, (uint32_t)((u - 1) & 1));

        // stage B via cp.async (pre-swizzled, direct GMEM->SMEM)
        {
            const char* bh = (const char*)g_Bhi + c * 16384 + tid * 16;
            const char* bl = (const char*)g_Blo + c * 16384 + tid * 16;
            uint32_t dh = bufb + 32768 + tid * 16;
            uint32_t dl = bufb + 49152 + tid * 16;
            #pragma unroll
            for (int i = 0; i < 4; i++) {
                cp16(dh + i * 4096, bh + i * 4096);
                cp16(dl + i * 4096, bl + i * 4096);
            }
            asm volatile("cp.async.commit_group;" ::: "memory");
        }
        // stage A: load H fp32, split hi/lo, swizzled STS
        #pragma unroll
        for (int it = 0; it < 4; it++) {
            int task = it * 256 + tid;
            int r = task >> 3, kq = task & 7;
            const float* hp = H + (size_t)(row0 + r) * KDIM + c * 64 + kq * 8;
            float4 u0 = *(const float4*)hp;
            float4 u1 = *(const float4*)(hp + 4);
            uint32_t hi[4], lo[4];
            bf16split(u0.x, u0.y, hi[0], lo[0]);
            bf16split(u0.z, u0.w, hi[1], lo[1]);
            bf16split(u1.x, u1.y, hi[2], lo[2]);
            bf16split(u1.z, u1.w, hi[3], lo[3]);
            int off = r * 128 + kq * 16;
            int swo = off ^ ((off >> 3) & 0x70);
            *(uint4*)(buf + swo)         = make_uint4(hi[0], hi[1], hi[2], hi[3]);
            *(uint4*)(buf + 16384 + swo) = make_uint4(lo[0], lo[1], lo[2], lo[3]);
        }
        asm volatile("cp.async.wait_group 0;" ::: "memory");
        asm volatile("fence.proxy.async.shared::cta;" ::: "memory");
        __syncthreads();

        if (w == 0 && elect1()) {
            uint64_t ah = mkdesc(bufb);
            uint64_t al = mkdesc(bufb + 16384);
            uint64_t bh = mkdesc(bufb + 32768);
            uint64_t bl = mkdesc(bufb + 49152);
            #pragma unroll
            for (int ks = 0; ks < 4; ks++) {
                uint32_t en0 = (c == 0 && ks == 0) ? 0u : 1u;
                mma_f16_ss(tmem, ah + 2 * ks, bh + 2 * ks, IDESC_BF16, en0);
                mma_f16_ss(tmem, ah + 2 * ks, bl + 2 * ks, IDESC_BF16, 1u);
                mma_f16_ss(tmem, al + 2 * ks, bh + 2 * ks, IDESC_BF16, 1u);
            }
            TC_COMMIT(sb + 16 + st * 8);
        }
    }

    // stage-1 barrier: in-loop waits consumed phases 0..4; last commit = phase 5 (parity 1).
    MBAR_WAITP(sb + 24, 1u);
    asm volatile("tcgen05.fence::after_thread_sync;" ::: "memory");

    if (w < 4) {
        #pragma unroll
        for (int base = 0; base < 128; base += 32) {
            uint32_t dr[32];
            LDTM32(dr, tmem + base);
            TC_WAITLD();
            float* op = g_sim + (size_t)(row0 + w * 32 + lane) * CDIM + base;
            #pragma unroll
            for (int j = 0; j < 32; j += 4) {
                float4 o;
                o.x = __uint_as_float(dr[j + 0]) + sbias[base + j + 0];
                o.y = __uint_as_float(dr[j + 1]) + sbias[base + j + 1];
                o.z = __uint_as_float(dr[j + 2]) + sbias[base + j + 2];
                o.w = __uint_as_float(dr[j + 3]) + sbias[base + j + 3];
                *(float4*)(op + j) = o;
            }
        }
        asm volatile("tcgen05.fence::before_thread_sync;" ::: "memory");
    }
    __syncthreads();
    if (w == 0) {
        asm volatile("tcgen05.dealloc.cta_group::1.sync.aligned.b32 %0, %1;"
                     :: "r"(tmem), "r"(128u));
    }
#else
    // Generic-arch fallback (never executed on sm_103a; keeps compute_103 PTX legal).
    extern __shared__ __align__(1024) char smem[];
    float (*As)[128] = (float(*)[128])smem;            // [16][128]
    float (*Bs)[128] = (float(*)[128])(smem + 8192);   // [16][128]
    int tid = threadIdx.x;
    int row0 = blockIdx.x << 7;
    int ty = tid >> 4, tx = tid & 15;
    float acc[8][8] = {};
    const float* Hb = H + (size_t)row0 * KDIM;
    for (int kt = 0; kt < KDIM; kt += 16) {
        #pragma unroll
        for (int i = 0; i < 2; i++) {
            int id = tid + i * 256;
            int m = id >> 2, kk = (id & 3) << 2;
            float4 v = *(const float4*)(Hb + (size_t)m * KDIM + kt + kk);
            As[kk + 0][m] = v.x; As[kk + 1][m] = v.y;
            As[kk + 2][m] = v.z; As[kk + 3][m] = v.w;
        }
        #pragma unroll
        for (int i = 0; i < 2; i++) {
            int id = tid + i * 256;
            int k = id >> 5, n4 = (id & 31) << 2;
            *(float4*)&Bs[k][n4] = *(const float4*)(g_A + (kt + k) * CDIM + n4);
        }
        __syncthreads();
        #pragma unroll
        for (int k = 0; k < 16; k++) {
            float a[8], b[8];
            #pragma unroll
            for (int i = 0; i < 8; i++) a[i] = As[k][ty * 8 + i];
            #pragma unroll
            for (int j = 0; j < 8; j++) b[j] = Bs[k][tx * 8 + j];
            #pragma unroll
            for (int i = 0; i < 8; i++)
                #pragma unroll
                for (int j = 0; j < 8; j++) acc[i][j] += a[i] * b[j];
        }
        __syncthreads();
    }
    #pragma unroll
    for (int i = 0; i < 8; i++) {
        size_t r = row0 + ty * 8 + i;
        float* op = g_sim + r * CDIM + tx * 8;
        #pragma unroll
        for (int j = 0; j < 8; j++) op[j] = acc[i][j] + g_bias[tx * 8 + j];
    }
#endif
}

// ================= P5: node_w = emb @ pool (4 nodes/block, float4 ILP) =================
__global__ __launch_bounds__(256) void pNw_kernel(const float* __restrict__ emb,
                                                  const float* __restrict__ pool) {
    __shared__ float se[4][16];
    int n0 = blockIdx.x << 2, tid = threadIdx.x;
    if (tid < 64) se[tid >> 4][tid & 15] = emb[(n0 + (tid >> 4)) * D_EMB + (tid & 15)];
    __syncthreads();
    float e0[16], e1[16], e2[16], e3[16];
    #pragma unroll
    for (int d = 0; d < 16; d++) {
        e0[d] = se[0][d]; e1[d] = se[1][d]; e2[d] = se[2][d]; e3[d] = se[3][d];
    }
    const float4* p4 = (const float4*)pool;
    #pragma unroll
    for (int j = 0; j < 4; j++) {
        int o = j * 256 + tid;
        float4 a0 = {0, 0, 0, 0}, a1 = a0, a2 = a0, a3 = a0;
        #pragma unroll
        for (int d = 0; d < 16; d++) {
            float4 pv = p4[d * 1024 + o];
            a0.x += e0[d] * pv.x; a0.y += e0[d] * pv.y; a0.z += e0[d] * pv.z; a0.w += e0[d] * pv.w;
            a1.x += e1[d] * pv.x; a1.y += e1[d] * pv.y; a1.z += e1[d] * pv.z; a1.w += e1[d] * pv.w;
            a2.x += e2[d] * pv.x; a2.y += e2[d] * pv.y; a2.z += e2[d] * pv.z; a2.w += e2[d] * pv.w;
            a3.x += e3[d] * pv.x; a3.y += e3[d] * pv.y; a3.z += e3[d] * pv.z; a3.w += e3[d] * pv.w;
        }
        float4* nw4 = (float4*)g_nw;
        nw4[(size_t)(n0 + 0) * 1024 + o] = a0;
        nw4[(size_t)(n0 + 1) * 1024 + o] = a1;
        nw4[(size_t)(n0 + 2) * 1024 + o] = a2;
        nw4[(size_t)(n0 + 3) * 1024 + o] = a3;
    }
}

// ================= K2: softmax + context + per-node projection =================
__global__ __launch_bounds__(256) void k2_epi(float* __restrict__ out) {
    __shared__ float snw[64][64];
    __shared__ float sLm[64][32];
    __shared__ float sGm[64][32];
    __shared__ float sattn[8][128];
    __shared__ float sfused[8][64];

    int n = blockIdx.x, tid = threadIdx.x;
    int w = tid >> 5, lane = tid & 31;

    {
        const float4* src = (const float4*)(g_nw + (size_t)n * 4096);
        float4* dst = (float4*)&snw[0][0];
        #pragma unroll
        for (int i = 0; i < 4; i++) dst[tid + i * 256] = src[tid + i * 256];
        float* lm = &sLm[0][0]; float* gm = &sGm[0][0];
        for (int i = tid; i < 2048; i += 256) { lm[i] = g_Lm[i]; gm[i] = g_Gm[i]; }
    }
    __syncthreads();

    for (int i = 0; i < 8; i++) {
        int b = i * 8 + w;
        size_t row = (size_t)b * N_NODES + n;
        const float* sp = g_sim + row * CDIM;
        float v0 = sp[lane], v1 = sp[lane + 32];
        float v2 = sp[lane + 64], v3 = sp[lane + 96];

        float mx = fmaxf(v0, v1);
        #pragma unroll
        for (int o = 16; o; o >>= 1) mx = fmaxf(mx, __shfl_xor_sync(0xffffffffu, mx, o));
        float e0 = __expf(v0 - mx), e1 = __expf(v1 - mx);
        float s = e0 + e1;
        #pragma unroll
        for (int o = 16; o; o >>= 1) s += __shfl_xor_sync(0xffffffffu, s, o);
        float inv = 1.f / s;
        sattn[w][lane] = e0 * inv; sattn[w][lane + 32] = e1 * inv;

        mx = fmaxf(v2, v3);
        #pragma unroll
        for (int o = 16; o; o >>= 1) mx = fmaxf(mx, __shfl_xor_sync(0xffffffffu, mx, o));
        float e2 = __expf(v2 - mx), e3 = __expf(v3 - mx);
        s = e2 + e3;
        #pragma unroll
        for (int o = 16; o; o >>= 1) s += __shfl_xor_sync(0xffffffffu, s, o);
        inv = 1.f / s;
        sattn[w][64 + lane] = e2 * inv; sattn[w][96 + lane] = e3 * inv;
        __syncwarp();

        float lctx = 0.f, gctx = 0.f;
        #pragma unroll 8
        for (int m = 0; m < 64; m++) {
            lctx += sattn[w][m]      * sLm[m][lane];
            gctx += sattn[w][64 + m] * sGm[m][lane];
        }
        sfused[w][lane] = lctx; sfused[w][lane + 32] = gctx;
        __syncwarp();

        float o0 = 0.f, o1 = 0.f;
        #pragma unroll 8
        for (int f = 0; f < 64; f++) {
            float fv = sfused[w][f];
            o0 += fv * snw[f][lane];
            o1 += fv * snw[f][lane + 32];
        }
        float* op = out + row * HID;
        op[lane] = o0; op[lane + 32] = o1;
        __syncwarp();
    }
}

// ================= launch =================
extern "C" void kernel_launch(void* const* d_in, const int* in_sizes, int n_in,
                              void* d_out, int out_size) {
    const float* H    = (const float*)d_in[0];   // [64,1024,12,64]
    const float* G    = (const float*)d_in[1];   // [64,6,32]
    const float* L    = (const float*)d_in[2];   // [64,12,32]
    const float* Wq   = (const float*)d_in[3];   // [64,32]
    const float* bq   = (const float*)d_in[4];   // [32]
    const float* emb  = (const float*)d_in[5];   // [1024,16]
    const float* pool = (const float*)d_in[6];   // [16,64,64]
    float* out = (float*)d_out;                  // [64,1024,64]

    static bool attr_done = false;
    if (!attr_done) {
        cudaFuncSetAttribute(k1_tc, cudaFuncAttributeMaxDynamicSharedMemorySize, K1_SMEM);
        attr_done = true;
    }

    // Order chosen so k1_tc sits in ncu's captured launch slot (0-based 3).
    pA_kernel   <<<128, 256>>>(G, L, Wq);        // slot 0
    pBias_kernel<<<1, 128>>>(G, L, bq);          // slot 1
    pBsw_kernel <<<48, 256>>>();                 // slot 2
    k1_tc       <<<ROWS / 128, 256, K1_SMEM>>>(H); // slot 3  <-- profiled
    pMean_kernel<<<8, 256>>>(G, L);              // slot 4
    pNw_kernel  <<<256, 256>>>(emb, pool);       // slot 5
    k2_epi      <<<N_NODES, 256>>>(out);         // slot 6
}